// round 15
// baseline (speedup 1.0000x reference)
#include <cuda_runtime.h>
#include <cuda_fp16.h>
#include <math.h>

#define S_     2048
#define HID_   2048
#define H_     16
#define HKV_   4
#define D_     128
#define GROUPS_ 4
#define SCALE_ 0.08838834764831845f   // 128^-0.5
#define DECAY_CUT (-25.0f)
#define SSCALE 512.0f
#define INV_SSCALE (1.0f/512.0f)

// ---------------- scratch (no cudaMalloc allowed) ----------------
__device__ float    g_q    [S_*H_*D_];          // unroped; rope applied in attn loader
__device__ float    g_k    [S_*HKV_*D_];
__device__ float    g_v    [S_*HKV_*D_];
__device__ float    g_g    [S_*HKV_];
__device__ float    g_gc   [HKV_*S_];
__device__ __half   g_attnh[S_*H_*D_];
__device__ __half   g_hsh  [S_*HID_];
__device__ unsigned g_wqp  [(HID_/2)*(H_*D_)];
__device__ unsigned g_wkp  [(HID_/2)*(HKV_*D_)];
__device__ unsigned g_wvp  [(HID_/2)*(HKV_*D_)];
__device__ unsigned g_wop  [((H_*D_)/2)*HID_];

// ---------------- helpers ----------------
__device__ __forceinline__ unsigned packh2(float lo, float hi) {
    __half2 h = __floats2half2_rn(lo, hi);
    return *(unsigned*)&h;
}
__device__ __forceinline__ unsigned sp_hi(float a, float b, unsigned& lo) {
    const __half ha = __float2half_rn(a), hb = __float2half_rn(b);
    lo = packh2(a - __half2float(ha), b - __half2float(hb));
    const __half2 hh = __halves2half2(ha, hb);
    return *(unsigned*)&hh;
}
__device__ __forceinline__ void mma_f16(float c[4], const unsigned a[4], const unsigned b[2]) {
    asm volatile("mma.sync.aligned.m16n8k16.row.col.f32.f16.f16.f32 "
        "{%0,%1,%2,%3},{%4,%5,%6,%7},{%8,%9},{%0,%1,%2,%3};"
        : "+f"(c[0]), "+f"(c[1]), "+f"(c[2]), "+f"(c[3])
        : "r"(a[0]), "r"(a[1]), "r"(a[2]), "r"(a[3]), "r"(b[0]), "r"(b[1]));
}
__device__ __forceinline__ void ldsm_x4(unsigned r[4], unsigned saddr) {
    asm volatile("ldmatrix.sync.aligned.m8n8.x4.shared.b16 {%0,%1,%2,%3}, [%4];"
        : "=r"(r[0]), "=r"(r[1]), "=r"(r[2]), "=r"(r[3]) : "r"(saddr));
}
__device__ __forceinline__ void cpa16(void* sp, const void* gp) {
    unsigned s = (unsigned)__cvta_generic_to_shared(sp);
    asm volatile("cp.async.cg.shared.global [%0], [%1], 16;" :: "r"(s), "l"(gp));
}

// ---------------- f32 -> fp16 conversions ----------------
__global__ void tohalf_plain(const float* __restrict__ s, __half* __restrict__ d) {
    const size_t i = ((size_t)blockIdx.x * 256 + threadIdx.x) * 4;
    float4 v = *(const float4*)(s + i);
    uint2 u;
    u.x = packh2(v.x, v.y);
    u.y = packh2(v.z, v.w);
    *(uint2*)((unsigned*)d + i / 2) = u;
}
__global__ void tohalf_pair(const float* __restrict__ W, unsigned* __restrict__ Wp, int N) {
    const int idx = blockIdx.x * 256 + threadIdx.x;
    const int nc4 = N / 4;
    const int kp = idx / nc4, c4 = (idx % nc4) * 4;
    const float4 w0 = *(const float4*)(W + (size_t)(2 * kp) * N + c4);
    const float4 w1 = *(const float4*)(W + (size_t)(2 * kp + 1) * N + c4);
    uint4 u;
    u.x = packh2(w0.x, w1.x);
    u.y = packh2(w0.y, w1.y);
    u.z = packh2(w0.z, w1.z);
    u.w = packh2(w0.w, w1.w);
    *(uint4*)(Wp + (size_t)kp * N + c4) = u;
}

// ---------------- fp16 tensor-core GEMM (BK=64, 3-stage, occ 2) -----------
#define BM 128
#define BN 128
#define NK 32                       // 2048 / 64
#define PAH 36                      // A pitch (u32): 32 data + 4 pad
#define PBH 136
#define STG_AH (128*PAH)            // 4608 u32
#define STG_BH (32*PBH)             // 4352 u32
#define GEMM_SMEMH (3*(STG_AH+STG_BH)*4)   // 107520 B

__device__ __forceinline__ void gemmh_issue(const __half* __restrict__ A,
        const unsigned* __restrict__ Bp, int N, int bm, int bn,
        unsigned* As, unsigned* Bs, int kt,
        int arow, int apair, int brow, int bcol) {
    unsigned* Ad = As + (kt % 3) * STG_AH;
    const unsigned* Ag = (const unsigned*)A + (size_t)(bm + arow) * 1024 + kt * 32 + apair;
    cpa16(Ad + arow * PAH + apair,      Ag);
    cpa16(Ad + arow * PAH + apair + 4,  Ag + 4);
    cpa16(Ad + arow * PAH + apair + 8,  Ag + 8);
    cpa16(Ad + arow * PAH + apair + 12, Ag + 12);
    unsigned* Bd = Bs + (kt % 3) * STG_BH;
    const unsigned* Bg = Bp + (size_t)(kt * 32 + brow) * N + bn + bcol;
    cpa16(Bd + brow * PBH + bcol,      Bg);
    cpa16(Bd + brow * PBH + bcol + 4,  Bg + 4);
    cpa16(Bd + brow * PBH + bcol + 8,  Bg + 8);
    cpa16(Bd + brow * PBH + bcol + 12, Bg + 12);
    asm volatile("cp.async.commit_group;");
}

__device__ __forceinline__ void gemmh_core(const __half* __restrict__ A,
        const unsigned* __restrict__ Bp, float* __restrict__ C,
        int N, int bm, int bn, unsigned* As, unsigned* Bs) {
    const int tid  = threadIdx.x;
    const int lane = tid & 31;
    const int warp = tid >> 5;
    const int ly = lane >> 2, lx = lane & 3;
    const int wm = (warp & 3) * 32;
    const int wn = (warp >> 2) * 64;
    const int arow = tid >> 1, apair = (tid & 1) * 16;
    const int brow = tid >> 3, bcol = (tid & 7) * 16;
    const int lrow   = (lane & 7) + ((lane >> 3) & 1) * 8;
    const int lchunk = ((lane >> 4) & 1) * 4;
    const unsigned As_s = (unsigned)__cvta_generic_to_shared(As);

    float acc[2][8][4];
    #pragma unroll
    for (int mi = 0; mi < 2; mi++)
        #pragma unroll
        for (int ni = 0; ni < 8; ni++)
            #pragma unroll
            for (int r = 0; r < 4; r++) acc[mi][ni][r] = 0.f;

    gemmh_issue(A, Bp, N, bm, bn, As, Bs, 0, arow, apair, brow, bcol);
    gemmh_issue(A, Bp, N, bm, bn, As, Bs, 1, arow, apair, brow, bcol);

    for (int kt = 0; kt < NK; kt++) {
        asm volatile("cp.async.wait_group 1;");
        __syncthreads();

        const unsigned AbS = As_s + (((kt % 3) * STG_AH) << 2);
        const unsigned* Bb = Bs + (kt % 3) * STG_BH;
        #pragma unroll
        for (int ks2 = 0; ks2 < 4; ks2++) {
            const int kp0 = ks2 * 8;
            unsigned af[2][4], bf[8][2];
            #pragma unroll
            for (int mi = 0; mi < 2; mi++)
                ldsm_x4(af[mi], AbS + (((wm + mi * 16 + lrow) * PAH + kp0 + lchunk) << 2));
            #pragma unroll
            for (int ni = 0; ni < 8; ni++) {
                const int n = wn + ni * 8 + ly;
                bf[ni][0] = Bb[(kp0 + lx) * PBH + n];
                bf[ni][1] = Bb[(kp0 + 4 + lx) * PBH + n];
            }
            #pragma unroll
            for (int mi = 0; mi < 2; mi++)
                #pragma unroll
                for (int ni = 0; ni < 8; ni++)
                    mma_f16(acc[mi][ni], af[mi], bf[ni]);
        }
        __syncthreads();

        if (kt + 2 < NK)
            gemmh_issue(A, Bp, N, bm, bn, As, Bs, kt + 2, arow, apair, brow, bcol);
        else
            asm volatile("cp.async.commit_group;");
    }

    #pragma unroll
    for (int mi = 0; mi < 2; mi++) {
        const int r0 = bm + wm + mi * 16 + ly;
        #pragma unroll
        for (int ni = 0; ni < 8; ni++) {
            const int c0 = bn + wn + ni * 8 + 2 * lx;
            *(float2*)(C + (size_t)r0 * N + c0)       = make_float2(acc[mi][ni][0], acc[mi][ni][1]);
            *(float2*)(C + (size_t)(r0 + 8) * N + c0) = make_float2(acc[mi][ni][2], acc[mi][ni][3]);
        }
    }
}

__global__ void __launch_bounds__(256, 2) gemm_qkv(const __half* __restrict__ A) {
    extern __shared__ unsigned smu[];
    const int bx = blockIdx.x;
    const unsigned* Bp; float* Cm; int N, bn;
    if (bx < 16)      { Bp = g_wqp; Cm = g_q; N = 2048; bn = bx * 128; }
    else if (bx < 20) { Bp = g_wkp; Cm = g_k; N = 512;  bn = (bx - 16) * 128; }
    else              { Bp = g_wvp; Cm = g_v; N = 512;  bn = (bx - 20) * 128; }
    gemmh_core(A, Bp, Cm, N, blockIdx.y * BM, bn, smu, smu + 3 * STG_AH);
}

__global__ void __launch_bounds__(256, 2) gemm_wo(const __half* __restrict__ A,
        float* __restrict__ C) {
    extern __shared__ unsigned smu[];
    gemmh_core(A, g_wop, C, HID_, blockIdx.y * BM, blockIdx.x * BN, smu, smu + 3 * STG_AH);
}

// ---------------- gate projection (exact fp32) ----------------
__global__ void gate_proj(const float* __restrict__ hs, const float* __restrict__ Wg) {
    const int s = blockIdx.x;
    const int w = threadIdx.x >> 5, l = threadIdx.x & 31;
    const float* row = hs + (size_t)s * HID_;
    float acc = 0.f;
    for (int k = l; k < HID_; k += 32)
        acc = fmaf(row[k], Wg[k * HKV_ + w], acc);
    #pragma unroll
    for (int o = 16; o > 0; o >>= 1)
        acc += __shfl_down_sync(0xffffffffu, acc, o);
    if (l == 0) g_g[s * HKV_ + w] = acc;
}

// ---------------- log-sigmoid + parallel cumsum ----------------
__global__ void gcumsum_kernel() {
    __shared__ float ps[256];
    const int kv = blockIdx.x;
    const int t = threadIdx.x;
    float loc[8]; float s = 0.f;
    #pragma unroll
    for (int i = 0; i < 8; i++) {
        const float x = g_g[(t * 8 + i) * HKV_ + kv];
        const float ls = (x > 0.f) ? -log1pf(__expf(-x)) : x - log1pf(__expf(x));
        loc[i] = ls; s += ls;
    }
    ps[t] = s; __syncthreads();
    for (int o = 1; o < 256; o <<= 1) {
        const float v = (t >= o) ? ps[t - o] : 0.f;
        __syncthreads();
        ps[t] += v;
        __syncthreads();
    }
    float run = (t > 0) ? ps[t - 1] : 0.f;
    #pragma unroll
    for (int i = 0; i < 8; i++) {
        run += loc[i];
        g_gc[kv * S_ + t * 8 + i] = run;
    }
}

// ---------------- fp16-split tensor-core power attention (R11) -----------
#define PQ2 68
#define PS2 36
#define PV2 136
#define ATTN_SMEM ((4*64*PQ2 + 2*32*PV2 + 192) * 4)   // 105216 B

__global__ void __launch_bounds__(256, 2) attn_kernel(
        const float* __restrict__ cosb, const float* __restrict__ sinb) {
    extern __shared__ unsigned smu[];
    unsigned* Qhi = smu;
    unsigned* Qlo = Qhi + 64 * PQ2;
    unsigned* Khi = Qlo + 64 * PQ2;
    unsigned* Klo = Khi + 64 * PQ2;
    unsigned* Vhi = Klo + 64 * PQ2;
    unsigned* Vlo = Vhi + 32 * PV2;
    float* Gq  = (float*)(Vlo + 32 * PV2);
    float* Gk  = Gq + 64;
    float* den = Gk + 64;
    unsigned* Shi = Khi;
    unsigned* Slo = Klo;

    const unsigned Qhi_s = (unsigned)__cvta_generic_to_shared(Qhi);
    const unsigned Qlo_s = Qhi_s + 64 * PQ2 * 4;
    const unsigned Khi_s = Qlo_s + 64 * PQ2 * 4;
    const unsigned Klo_s = Khi_s + 64 * PQ2 * 4;
    const unsigned Shi_s = Khi_s;
    const unsigned Slo_s = Klo_s;

    const int qb = gridDim.x - 1 - blockIdx.x;
    const int h = blockIdx.y, kv = h / GROUPS_;
    const int tid  = threadIdx.x;
    const int lane = tid & 31, warp = tid >> 5;
    const int ly = lane >> 2, lx = lane & 3;
    const int wm  = (warp & 3) * 16;
    const int wn  = (warp >> 2) * 32;
    const int wn2 = (warp >> 2) * 64;
    const int lrow   = (lane & 7) + ((lane >> 3) & 1) * 8;
    const int lchunk = ((lane >> 4) & 1) * 4;
    const int krow   = (lane & 7) + ((lane >> 4) & 1) * 8;
    const int kchunk = ((lane >> 3) & 1) * 4;

    #pragma unroll
    for (int j = 0; j < 8; j++) {
        const int idx = j * 256 + tid;
        const int r = idx >> 5, d0 = (idx & 31) * 4;
        const int srow = qb * 64 + r;
        const float* base = g_q + (size_t)srow * (H_ * D_) + h * D_;
        const float4 x  = *(const float4*)(base + d0);
        const float4 y  = *(const float4*)(base + (d0 ^ 64));
        const float4 c4 = *(const float4*)(cosb + srow * 128 + d0);
        const float4 s4 = *(const float4*)(sinb + srow * 128 + d0);
        const float sg = (d0 < 64) ? -1.f : 1.f;
        const float r0 = x.x * c4.x + sg * y.x * s4.x;
        const float r1 = x.y * c4.y + sg * y.y * s4.y;
        const float r2 = x.z * c4.z + sg * y.z * s4.z;
        const float r3 = x.w * c4.w + sg * y.w * s4.w;
        unsigned l0, l1;
        const unsigned h0 = sp_hi(r0, r1, l0);
        const unsigned h1 = sp_hi(r2, r3, l1);
        Qhi[r * PQ2 + d0 / 2]     = h0;
        Qhi[r * PQ2 + d0 / 2 + 1] = h1;
        Qlo[r * PQ2 + d0 / 2]     = l0;
        Qlo[r * PQ2 + d0 / 2 + 1] = l1;
    }
    if (tid < 64) { Gq[tid] = g_gc[kv * S_ + qb * 64 + tid]; den[tid] = 0.f; }
    __syncthreads();

    const float gq0 = Gq[wm + ly];
    const float gq1 = Gq[wm + ly + 8];
    const float Gq0 = Gq[0];

    float o[8][4];
    #pragma unroll
    for (int ni = 0; ni < 8; ni++)
        #pragma unroll
        for (int r = 0; r < 4; r++) o[ni][r] = 0.f;
    float rs0 = 0.f, rs1 = 0.f;

    for (int kb = qb; kb >= 0; kb--) {
        if (kb < qb && Gq0 - g_gc[kv * S_ + kb * 64 + 63] < DECAY_CUT) break;
        __syncthreads();

        #pragma unroll
        for (int j = 0; j < 8; j++) {
            const int idx = j * 256 + tid;
            const int r = idx >> 5, d0 = (idx & 31) * 4;
            const int srow = kb * 64 + r;
            const float* base = g_k + (size_t)srow * (HKV_ * D_) + kv * D_;
            const float4 x  = *(const float4*)(base + d0);
            const float4 y  = *(const float4*)(base + (d0 ^ 64));
            const float4 c4 = *(const float4*)(cosb + srow * 128 + d0);
            const float4 s4 = *(const float4*)(sinb + srow * 128 + d0);
            const float sg = (d0 < 64) ? -1.f : 1.f;
            const float r0 = x.x * c4.x + sg * y.x * s4.x;
            const float r1 = x.y * c4.y + sg * y.y * s4.y;
            const float r2 = x.z * c4.z + sg * y.z * s4.z;
            const float r3 = x.w * c4.w + sg * y.w * s4.w;
            unsigned l0, l1;
            const unsigned h0 = sp_hi(r0, r1, l0);
            const unsigned h1 = sp_hi(r2, r3, l1);
            Khi[r * PQ2 + d0 / 2]     = h0;
            Khi[r * PQ2 + d0 / 2 + 1] = h1;
            Klo[r * PQ2 + d0 / 2]     = l0;
            Klo[r * PQ2 + d0 / 2 + 1] = l1;
        }
        #pragma unroll
        for (int j = 0; j < 4; j++) {
            const int idx = j * 256 + tid;
            const int kp = idx >> 5, n0 = (idx & 31) * 4;
            const size_t b0 = (size_t)(kb * 64 + 2 * kp) * (HKV_ * D_) + kv * D_ + n0;
            const float4 v0 = *(const float4*)(g_v + b0);
            const float4 v1 = *(const float4*)(g_v + b0 + HKV_ * D_);
            unsigned l0, l1, l2, l3;
            Vhi[kp * PV2 + n0 + 0] = sp_hi(v0.x, v1.x, l0);
            Vhi[kp * PV2 + n0 + 1] = sp_hi(v0.y, v1.y, l1);
            Vhi[kp * PV2 + n0 + 2] = sp_hi(v0.z, v1.z, l2);
            Vhi[kp * PV2 + n0 + 3] = sp_hi(v0.w, v1.w, l3);
            Vlo[kp * PV2 + n0 + 0] = l0;
            Vlo[kp * PV2 + n0 + 1] = l1;
            Vlo[kp * PV2 + n0 + 2] = l2;
            Vlo[kp * PV2 + n0 + 3] = l3;
        }
        if (tid < 64) Gk[tid] = g_gc[kv * S_ + kb * 64 + tid];
        __syncthreads();

        float c[4][4];
        #pragma unroll
        for (int ni = 0; ni < 4; ni++)
            #pragma unroll
            for (int r = 0; r < 4; r++) c[ni][r] = 0.f;
        #pragma unroll
        for (int ks2 = 0; ks2 < 8; ks2++) {
            const int kp0 = ks2 * 8;
            unsigned ah[4], al[4];
            const unsigned qoff = (((wm + lrow) * PQ2 + kp0 + lchunk) << 2);
            ldsm_x4(ah, Qhi_s + qoff);
            ldsm_x4(al, Qlo_s + qoff);
            #pragma unroll
            for (int nb = 0; nb < 2; nb++) {
                const unsigned koff = (((wn + nb * 16 + krow) * PQ2 + kp0 + kchunk) << 2);
                unsigned bh4[4], bl4[4];
                ldsm_x4(bh4, Khi_s + koff);
                ldsm_x4(bl4, Klo_s + koff);
                mma_f16(c[2 * nb],     ah, &bh4[0]);
                mma_f16(c[2 * nb],     al, &bh4[0]);
                mma_f16(c[2 * nb],     ah, &bl4[0]);
                mma_f16(c[2 * nb + 1], ah, &bh4[2]);
                mma_f16(c[2 * nb + 1], al, &bh4[2]);
                mma_f16(c[2 * nb + 1], ah, &bl4[2]);
            }
        }
        float gk0v[4], gk1v[4];
        #pragma unroll
        for (int ni = 0; ni < 4; ni++) {
            const int col = wn + ni * 8 + 2 * lx;
            gk0v[ni] = Gk[col];
            gk1v[ni] = Gk[col + 1];
        }
        __syncthreads();

        const int rg0 = qb * 64 + wm + ly;
        const int rg1 = rg0 + 8;
        #pragma unroll
        for (int ni = 0; ni < 4; ni++) {
            const int col = wn + ni * 8 + 2 * lx;
            const int cg  = kb * 64 + col;
            float t;
            t = c[ni][0] * SCALE_;
            const float v00 = (cg     <= rg0) ? t * t * __expf(gq0 - gk0v[ni]) : 0.f;
            t = c[ni][1] * SCALE_;
            const float v01 = (cg + 1 <= rg0) ? t * t * __expf(gq0 - gk1v[ni]) : 0.f;
            t = c[ni][2] * SCALE_;
            const float v10 = (cg     <= rg1) ? t * t * __expf(gq1 - gk0v[ni]) : 0.f;
            t = c[ni][3] * SCALE_;
            const float v11 = (cg + 1 <= rg1) ? t * t * __expf(gq1 - gk1v[ni]) : 0.f;
            rs0 += v00 + v01;
            rs1 += v10 + v11;
            const int sp = wn / 2 + 4 * ni + lx;
            unsigned l0, l1;
            Shi[(wm + ly) * PS2 + sp]     = sp_hi(v00 * SSCALE, v01 * SSCALE, l0);
            Shi[(wm + ly + 8) * PS2 + sp] = sp_hi(v10 * SSCALE, v11 * SSCALE, l1);
            Slo[(wm + ly) * PS2 + sp]     = l0;
            Slo[(wm + ly + 8) * PS2 + sp] = l1;
        }
        __syncthreads();

        #pragma unroll
        for (int ks2 = 0; ks2 < 4; ks2++) {
            const int jp0 = ks2 * 8;
            unsigned ah[4], al[4];
            const unsigned soff = (((wm + lrow) * PS2 + jp0 + lchunk) << 2);
            ldsm_x4(ah, Shi_s + soff);
            ldsm_x4(al, Slo_s + soff);
            #pragma unroll
            for (int ni = 0; ni < 8; ni++) {
                const int n = wn2 + ni * 8 + ly;
                unsigned bh[2], bl[2];
                bh[0] = Vhi[(jp0 + lx) * PV2 + n];
                bh[1] = Vhi[(jp0 + 4 + lx) * PV2 + n];
                bl[0] = Vlo[(jp0 + lx) * PV2 + n];
                bl[1] = Vlo[(jp0 + 4 + lx) * PV2 + n];
                mma_f16(o[ni], ah, bh);
                mma_f16(o[ni], al, bh);
                mma_f16(o[ni], ah, bl);
            }
        }
    }

    rs0 += __shfl_xor_sync(0xffffffffu, rs0, 1);
    rs0 += __shfl_xor_sync(0xffffffffu, rs0, 2);
    rs1 += __shfl_xor_sync(0xffffffffu, rs1, 1);
    rs1 += __shfl_xor_sync(0xffffffffu, rs1, 2);
    if (lx == 0) {
        atomicAdd(&den[wm + ly], rs0);
        atomicAdd(&den[wm + ly + 8], rs1);
    }
    __syncthreads();

    const float inv0 = INV_SSCALE / fmaxf(den[wm + ly], 1.f);
    const float inv1 = INV_SSCALE / fmaxf(den[wm + ly + 8], 1.f);
    unsigned* ah32 = (unsigned*)g_attnh;
    #pragma unroll
    for (int ni = 0; ni < 8; ni++) {
        const int colg = h * D_ + wn2 + ni * 8 + 2 * lx;
        const size_t i0 = ((size_t)(qb * 64 + wm + ly) * (H_ * D_) + colg) / 2;
        const size_t i1 = ((size_t)(qb * 64 + wm + ly + 8) * (H_ * D_) + colg) / 2;
        ah32[i0] = packh2(o[ni][0] * inv0, o[ni][1] * inv0);
        ah32[i1] = packh2(o[ni][2] * inv1, o[ni][3] * inv1);
    }
}

// ---------------- launch ----------------
extern "C" void kernel_launch(void* const* d_in, const int* in_sizes, int n_in,
                              void* d_out, int out_size) {
    (void)in_sizes; (void)n_in; (void)out_size;
    const float* hs   = (const float*)d_in[0];
    const float* cosb = (const float*)d_in[1];
    const float* sinb = (const float*)d_in[2];
    const float* Wq   = (const float*)d_in[3];
    const float* Wk   = (const float*)d_in[4];
    const float* Wv   = (const float*)d_in[5];
    const float* Wg   = (const float*)d_in[6];
    const float* Wo   = (const float*)d_in[7];
    float* out = (float*)d_out;

    __half *hsh, *attnh;
    unsigned *wqp, *wkp, *wvp, *wop;
    cudaGetSymbolAddress((void**)&hsh,   g_hsh);
    cudaGetSymbolAddress((void**)&attnh, g_attnh);
    cudaGetSymbolAddress((void**)&wqp,   g_wqp);
    cudaGetSymbolAddress((void**)&wkp,   g_wkp);
    cudaGetSymbolAddress((void**)&wvp,   g_wvp);
    cudaGetSymbolAddress((void**)&wop,   g_wop);

    static cudaStream_t s1 = nullptr, s2 = nullptr, s3 = nullptr;
    static cudaEvent_t ev0, ev1, ev2, ev2a, ev3;
    if (!s1) {
        cudaStreamCreateWithFlags(&s1, cudaStreamNonBlocking);
        cudaStreamCreateWithFlags(&s2, cudaStreamNonBlocking);
        cudaStreamCreateWithFlags(&s3, cudaStreamNonBlocking);
        cudaEventCreateWithFlags(&ev0,  cudaEventDisableTiming);
        cudaEventCreateWithFlags(&ev1,  cudaEventDisableTiming);
        cudaEventCreateWithFlags(&ev2,  cudaEventDisableTiming);
        cudaEventCreateWithFlags(&ev2a, cudaEventDisableTiming);
        cudaEventCreateWithFlags(&ev3,  cudaEventDisableTiming);
    }

    cudaFuncSetAttribute(gemm_qkv, cudaFuncAttributeMaxDynamicSharedMemorySize, GEMM_SMEMH);
    cudaFuncSetAttribute(gemm_wo,  cudaFuncAttributeMaxDynamicSharedMemorySize, GEMM_SMEMH);
    cudaFuncSetAttribute(attn_kernel, cudaFuncAttributeMaxDynamicSharedMemorySize, ATTN_SMEM);

    cudaEventRecord(ev0, 0);

    // side stream 2: Wq pair-pack
    cudaStreamWaitEvent(s2, ev0, 0);
    tohalf_pair<<<(HID_/2)*(H_*D_)/4/256, 256, 0, s2>>>(Wq, wqp, H_*D_);
    cudaEventRecord(ev2a, s2);

    // side stream 3: Wk, Wv, then Wo pair-packs
    cudaStreamWaitEvent(s3, ev0, 0);
    tohalf_pair<<<(HID_/2)*(HKV_*D_)/4/256, 256, 0, s3>>>(Wk, wkp, HKV_*D_);
    tohalf_pair<<<(HID_/2)*(HKV_*D_)/4/256, 256, 0, s3>>>(Wv, wvp, HKV_*D_);
    cudaEventRecord(ev3, s3);
    tohalf_pair<<<((H_*D_)/2)*HID_/4/256, 256, 0, s3>>>(Wo, wop, HID_);
    cudaEventRecord(ev2, s3);

    // side stream 1: gate path (exact fp32)
    cudaStreamWaitEvent(s1, ev0, 0);
    gate_proj<<<S_, 128, 0, s1>>>(hs, Wg);
    gcumsum_kernel<<<HKV_, 256, 0, s1>>>();
    cudaEventRecord(ev1, s1);

    // main stream
    tohalf_plain<<<(S_*HID_) / 1024, 256>>>(hs, hsh);
    cudaStreamWaitEvent(0, ev2a, 0);
    cudaStreamWaitEvent(0, ev3, 0);
    gemm_qkv<<<dim3(24, S_ / BM), 256, GEMM_SMEMH>>>(hsh);

    cudaStreamWaitEvent(0, ev1, 0);
    attn_kernel<<<dim3(S_ / 64, H_), 256, ATTN_SMEM>>>(cosb, sinb);

    cudaStreamWaitEvent(0, ev2, 0);
    gemm_wo<<<dim3(HID_ / BN, S_ / BM), 256, GEMM_SMEMH>>>(attnh, out);
}

// round 16
// speedup vs baseline: 1.1060x; 1.1060x over previous
#include <cuda_runtime.h>
#include <cuda_fp16.h>
#include <math.h>

#define S_     2048
#define HID_   2048
#define H_     16
#define HKV_   4
#define D_     128
#define GROUPS_ 4
#define SCALE_ 0.08838834764831845f   // 128^-0.5
#define DECAY_CUT (-25.0f)
#define SSCALE 512.0f
#define INV_SSCALE (1.0f/512.0f)

// ---------------- scratch (no cudaMalloc allowed) ----------------
__device__ float    g_q    [S_*H_*D_];          // unroped; rope applied in attn loader
__device__ float    g_k    [S_*HKV_*D_];
__device__ float    g_v    [S_*HKV_*D_];
__device__ float    g_g    [S_*HKV_];
__device__ float    g_gc   [HKV_*S_];
__device__ __half   g_attnh[S_*H_*D_];
__device__ __half   g_hsh  [S_*HID_];
__device__ unsigned g_wqp  [(HID_/2)*(H_*D_)];
__device__ unsigned g_wkp  [(HID_/2)*(HKV_*D_)];
__device__ unsigned g_wvp  [(HID_/2)*(HKV_*D_)];
__device__ unsigned g_wop  [((H_*D_)/2)*HID_];

// ---------------- helpers ----------------
__device__ __forceinline__ unsigned packh2(float lo, float hi) {
    __half2 h = __floats2half2_rn(lo, hi);
    return *(unsigned*)&h;
}
__device__ __forceinline__ unsigned sp_hi(float a, float b, unsigned& lo) {
    const __half ha = __float2half_rn(a), hb = __float2half_rn(b);
    lo = packh2(a - __half2float(ha), b - __half2float(hb));
    const __half2 hh = __halves2half2(ha, hb);
    return *(unsigned*)&hh;
}
__device__ __forceinline__ void mma_f16(float c[4], const unsigned a[4], const unsigned b[2]) {
    asm volatile("mma.sync.aligned.m16n8k16.row.col.f32.f16.f16.f32 "
        "{%0,%1,%2,%3},{%4,%5,%6,%7},{%8,%9},{%0,%1,%2,%3};"
        : "+f"(c[0]), "+f"(c[1]), "+f"(c[2]), "+f"(c[3])
        : "r"(a[0]), "r"(a[1]), "r"(a[2]), "r"(a[3]), "r"(b[0]), "r"(b[1]));
}
__device__ __forceinline__ void ldsm_x4(unsigned r[4], unsigned saddr) {
    asm volatile("ldmatrix.sync.aligned.m8n8.x4.shared.b16 {%0,%1,%2,%3}, [%4];"
        : "=r"(r[0]), "=r"(r[1]), "=r"(r[2]), "=r"(r[3]) : "r"(saddr));
}
__device__ __forceinline__ void cpa16(void* sp, const void* gp) {
    unsigned s = (unsigned)__cvta_generic_to_shared(sp);
    asm volatile("cp.async.cg.shared.global [%0], [%1], 16;" :: "r"(s), "l"(gp));
}

// ---------------- f32 -> fp16 conversions ----------------
__global__ void tohalf_plain(const float* __restrict__ s, __half* __restrict__ d) {
    const size_t i = ((size_t)blockIdx.x * 256 + threadIdx.x) * 4;
    float4 v = *(const float4*)(s + i);
    uint2 u;
    u.x = packh2(v.x, v.y);
    u.y = packh2(v.z, v.w);
    *(uint2*)((unsigned*)d + i / 2) = u;
}
__global__ void tohalf_pair(const float* __restrict__ W, unsigned* __restrict__ Wp, int N) {
    const int idx = blockIdx.x * 256 + threadIdx.x;
    const int nc4 = N / 4;
    const int kp = idx / nc4, c4 = (idx % nc4) * 4;
    const float4 w0 = *(const float4*)(W + (size_t)(2 * kp) * N + c4);
    const float4 w1 = *(const float4*)(W + (size_t)(2 * kp + 1) * N + c4);
    uint4 u;
    u.x = packh2(w0.x, w1.x);
    u.y = packh2(w0.y, w1.y);
    u.z = packh2(w0.z, w1.z);
    u.w = packh2(w0.w, w1.w);
    *(uint4*)(Wp + (size_t)kp * N + c4) = u;
}

// ---------------- fp16 tensor-core GEMM, BM=128 (R14, proven; Wo) --------
#define BM 128
#define BN 128
#define NK 64
#define PAH 20
#define PBH 136
#define STG_AH (128*PAH)
#define STG_BH (16*PBH)
#define GEMM_SMEMH (3*(STG_AH+STG_BH)*4)

__device__ __forceinline__ void gemmh_issue(const __half* __restrict__ A,
        const unsigned* __restrict__ Bp, int N, int bm, int bn,
        unsigned* As, unsigned* Bs, int kt,
        int arow, int apair, int brow, int bcol) {
    unsigned* Ad = As + (kt % 3) * STG_AH;
    const unsigned* Ag = (const unsigned*)A + (size_t)(bm + arow) * 1024 + kt * 16 + apair;
    cpa16(Ad + arow * PAH + apair,     Ag);
    cpa16(Ad + arow * PAH + apair + 4, Ag + 4);
    unsigned* Bd = Bs + (kt % 3) * STG_BH;
    const unsigned* Bg = Bp + (size_t)(kt * 16 + brow) * N + bn + bcol;
    cpa16(Bd + brow * PBH + bcol,     Bg);
    cpa16(Bd + brow * PBH + bcol + 4, Bg + 4);
    asm volatile("cp.async.commit_group;");
}

__device__ __forceinline__ void gemmh_core(const __half* __restrict__ A,
        const unsigned* __restrict__ Bp, float* __restrict__ C,
        int N, int bm, int bn, unsigned* As, unsigned* Bs) {
    const int tid  = threadIdx.x;
    const int lane = tid & 31;
    const int warp = tid >> 5;
    const int ly = lane >> 2, lx = lane & 3;
    const int wm = (warp & 3) * 32;
    const int wn = (warp >> 2) * 64;
    const int arow = tid >> 1, apair = (tid & 1) * 8;
    const int brow = tid >> 4, bcol = (tid & 15) * 8;
    const int lrow   = (lane & 7) + ((lane >> 3) & 1) * 8;
    const int lchunk = ((lane >> 4) & 1) * 4;
    const unsigned As_s = (unsigned)__cvta_generic_to_shared(As);

    float acc[2][8][4];
    #pragma unroll
    for (int mi = 0; mi < 2; mi++)
        #pragma unroll
        for (int ni = 0; ni < 8; ni++)
            #pragma unroll
            for (int r = 0; r < 4; r++) acc[mi][ni][r] = 0.f;

    gemmh_issue(A, Bp, N, bm, bn, As, Bs, 0, arow, apair, brow, bcol);
    gemmh_issue(A, Bp, N, bm, bn, As, Bs, 1, arow, apair, brow, bcol);

    for (int kt = 0; kt < NK; kt++) {
        asm volatile("cp.async.wait_group 1;");
        __syncthreads();

        const unsigned AbS = As_s + (((kt % 3) * STG_AH) << 2);
        const unsigned* Bb = Bs + (kt % 3) * STG_BH;
        #pragma unroll
        for (int ks2 = 0; ks2 < 2; ks2++) {
            const int kp0 = ks2 * 8;
            unsigned af[2][4], bf[8][2];
            #pragma unroll
            for (int mi = 0; mi < 2; mi++)
                ldsm_x4(af[mi], AbS + (((wm + mi * 16 + lrow) * PAH + kp0 + lchunk) << 2));
            #pragma unroll
            for (int ni = 0; ni < 8; ni++) {
                const int n = wn + ni * 8 + ly;
                bf[ni][0] = Bb[(kp0 + lx) * PBH + n];
                bf[ni][1] = Bb[(kp0 + 4 + lx) * PBH + n];
            }
            #pragma unroll
            for (int mi = 0; mi < 2; mi++)
                #pragma unroll
                for (int ni = 0; ni < 8; ni++)
                    mma_f16(acc[mi][ni], af[mi], bf[ni]);
        }
        __syncthreads();

        if (kt + 2 < NK)
            gemmh_issue(A, Bp, N, bm, bn, As, Bs, kt + 2, arow, apair, brow, bcol);
        else
            asm volatile("cp.async.commit_group;");
    }

    #pragma unroll
    for (int mi = 0; mi < 2; mi++) {
        const int r0 = bm + wm + mi * 16 + ly;
        #pragma unroll
        for (int ni = 0; ni < 8; ni++) {
            const int c0 = bn + wn + ni * 8 + 2 * lx;
            *(float2*)(C + (size_t)r0 * N + c0)       = make_float2(acc[mi][ni][0], acc[mi][ni][1]);
            *(float2*)(C + (size_t)(r0 + 8) * N + c0) = make_float2(acc[mi][ni][2], acc[mi][ni][3]);
        }
    }
}

__global__ void __launch_bounds__(256, 2) gemm_wo(const __half* __restrict__ A,
        float* __restrict__ C) {
    extern __shared__ unsigned smu[];
    gemmh_core(A, g_wop, C, HID_, blockIdx.y * BM, blockIdx.x * BN, smu, smu + 3 * STG_AH);
}

// ---------------- fp16 GEMM, BM=64 (QKV — better wave packing) -----------
#define BM64 64
#define STG_A64 (64*PAH)            // 1280 u32
#define GEMM_SMEM64 (3*(STG_A64+STG_BH)*4)   // 41472 B

__device__ __forceinline__ void gemm64_issue(const __half* __restrict__ A,
        const unsigned* __restrict__ Bp, int N, int bm, int bn,
        unsigned* As, unsigned* Bs, int kt,
        int arow, int achunk, int brow, int bcol) {
    unsigned* Ad = As + (kt % 3) * STG_A64;
    const unsigned* Ag = (const unsigned*)A + (size_t)(bm + arow) * 1024 + kt * 16 + achunk;
    cpa16(Ad + arow * PAH + achunk, Ag);
    unsigned* Bd = Bs + (kt % 3) * STG_BH;
    const unsigned* Bg = Bp + (size_t)(kt * 16 + brow) * N + bn + bcol;
    cpa16(Bd + brow * PBH + bcol,     Bg);
    cpa16(Bd + brow * PBH + bcol + 4, Bg + 4);
    asm volatile("cp.async.commit_group;");
}

__global__ void __launch_bounds__(256, 3) gemm_qkv(const __half* __restrict__ A) {
    extern __shared__ unsigned smu[];
    unsigned* As = smu;
    unsigned* Bs = smu + 3 * STG_A64;

    const int bx = blockIdx.x;
    const unsigned* Bp; float* C; int N, bn;
    if (bx < 16)      { Bp = g_wqp; C = g_q; N = 2048; bn = bx * 128; }
    else if (bx < 20) { Bp = g_wkp; C = g_k; N = 512;  bn = (bx - 16) * 128; }
    else              { Bp = g_wvp; C = g_v; N = 512;  bn = (bx - 20) * 128; }
    const int bm = blockIdx.y * BM64;

    const int tid  = threadIdx.x;
    const int lane = tid & 31;
    const int warp = tid >> 5;
    const int ly = lane >> 2, lx = lane & 3;
    const int wm = (warp & 1) * 32;       // 2 warps along M
    const int wn = (warp >> 1) * 32;      // 4 warps along N
    const int arow = tid >> 2, achunk = (tid & 3) * 4;
    const int brow = tid >> 4, bcol = (tid & 15) * 8;
    const int lrow   = (lane & 7) + ((lane >> 3) & 1) * 8;
    const int lchunk = ((lane >> 4) & 1) * 4;
    const unsigned As_s = (unsigned)__cvta_generic_to_shared(As);

    float acc[2][4][4];
    #pragma unroll
    for (int mi = 0; mi < 2; mi++)
        #pragma unroll
        for (int ni = 0; ni < 4; ni++)
            #pragma unroll
            for (int r = 0; r < 4; r++) acc[mi][ni][r] = 0.f;

    gemm64_issue(A, Bp, N, bm, bn, As, Bs, 0, arow, achunk, brow, bcol);
    gemm64_issue(A, Bp, N, bm, bn, As, Bs, 1, arow, achunk, brow, bcol);

    for (int kt = 0; kt < NK; kt++) {
        asm volatile("cp.async.wait_group 1;");
        __syncthreads();

        const unsigned AbS = As_s + (((kt % 3) * STG_A64) << 2);
        const unsigned* Bb = Bs + (kt % 3) * STG_BH;
        #pragma unroll
        for (int ks2 = 0; ks2 < 2; ks2++) {
            const int kp0 = ks2 * 8;
            unsigned af[2][4], bf[4][2];
            #pragma unroll
            for (int mi = 0; mi < 2; mi++)
                ldsm_x4(af[mi], AbS + (((wm + mi * 16 + lrow) * PAH + kp0 + lchunk) << 2));
            #pragma unroll
            for (int ni = 0; ni < 4; ni++) {
                const int n = wn + ni * 8 + ly;
                bf[ni][0] = Bb[(kp0 + lx) * PBH + n];
                bf[ni][1] = Bb[(kp0 + 4 + lx) * PBH + n];
            }
            #pragma unroll
            for (int mi = 0; mi < 2; mi++)
                #pragma unroll
                for (int ni = 0; ni < 4; ni++)
                    mma_f16(acc[mi][ni], af[mi], bf[ni]);
        }
        __syncthreads();

        if (kt + 2 < NK)
            gemm64_issue(A, Bp, N, bm, bn, As, Bs, kt + 2, arow, achunk, brow, bcol);
        else
            asm volatile("cp.async.commit_group;");
    }

    #pragma unroll
    for (int mi = 0; mi < 2; mi++) {
        const int r0 = bm + wm + mi * 16 + ly;
        #pragma unroll
        for (int ni = 0; ni < 4; ni++) {
            const int c0 = bn + wn + ni * 8 + 2 * lx;
            *(float2*)(C + (size_t)r0 * N + c0)       = make_float2(acc[mi][ni][0], acc[mi][ni][1]);
            *(float2*)(C + (size_t)(r0 + 8) * N + c0) = make_float2(acc[mi][ni][2], acc[mi][ni][3]);
        }
    }
}

// ---------------- gate projection (exact fp32) ----------------
__global__ void gate_proj(const float* __restrict__ hs, const float* __restrict__ Wg) {
    const int s = blockIdx.x;
    const int w = threadIdx.x >> 5, l = threadIdx.x & 31;
    const float* row = hs + (size_t)s * HID_;
    float acc = 0.f;
    for (int k = l; k < HID_; k += 32)
        acc = fmaf(row[k], Wg[k * HKV_ + w], acc);
    #pragma unroll
    for (int o = 16; o > 0; o >>= 1)
        acc += __shfl_down_sync(0xffffffffu, acc, o);
    if (l == 0) g_g[s * HKV_ + w] = acc;
}

// ---------------- log-sigmoid + parallel cumsum ----------------
__global__ void gcumsum_kernel() {
    __shared__ float ps[256];
    const int kv = blockIdx.x;
    const int t = threadIdx.x;
    float loc[8]; float s = 0.f;
    #pragma unroll
    for (int i = 0; i < 8; i++) {
        const float x = g_g[(t * 8 + i) * HKV_ + kv];
        const float ls = (x > 0.f) ? -log1pf(__expf(-x)) : x - log1pf(__expf(x));
        loc[i] = ls; s += ls;
    }
    ps[t] = s; __syncthreads();
    for (int o = 1; o < 256; o <<= 1) {
        const float v = (t >= o) ? ps[t - o] : 0.f;
        __syncthreads();
        ps[t] += v;
        __syncthreads();
    }
    float run = (t > 0) ? ps[t - 1] : 0.f;
    #pragma unroll
    for (int i = 0; i < 8; i++) {
        run += loc[i];
        g_gc[kv * S_ + t * 8 + i] = run;
    }
}

// ---------------- fp16-split tensor-core power attention (R11/R14) --------
#define PQ2 68
#define PS2 36
#define PV2 136
#define ATTN_SMEM ((4*64*PQ2 + 2*32*PV2 + 192) * 4)   // 105216 B

__global__ void __launch_bounds__(256, 2) attn_kernel(
        const float* __restrict__ cosb, const float* __restrict__ sinb) {
    extern __shared__ unsigned smu[];
    unsigned* Qhi = smu;
    unsigned* Qlo = Qhi + 64 * PQ2;
    unsigned* Khi = Qlo + 64 * PQ2;
    unsigned* Klo = Khi + 64 * PQ2;
    unsigned* Vhi = Klo + 64 * PQ2;
    unsigned* Vlo = Vhi + 32 * PV2;
    float* Gq  = (float*)(Vlo + 32 * PV2);
    float* Gk  = Gq + 64;
    float* den = Gk + 64;
    unsigned* Shi = Khi;
    unsigned* Slo = Klo;

    const unsigned Qhi_s = (unsigned)__cvta_generic_to_shared(Qhi);
    const unsigned Qlo_s = Qhi_s + 64 * PQ2 * 4;
    const unsigned Khi_s = Qlo_s + 64 * PQ2 * 4;
    const unsigned Klo_s = Khi_s + 64 * PQ2 * 4;
    const unsigned Shi_s = Khi_s;
    const unsigned Slo_s = Klo_s;

    const int qb = gridDim.x - 1 - blockIdx.x;
    const int h = blockIdx.y, kv = h / GROUPS_;
    const int tid  = threadIdx.x;
    const int lane = tid & 31, warp = tid >> 5;
    const int ly = lane >> 2, lx = lane & 3;
    const int wm  = (warp & 3) * 16;
    const int wn  = (warp >> 2) * 32;
    const int wn2 = (warp >> 2) * 64;
    const int lrow   = (lane & 7) + ((lane >> 3) & 1) * 8;
    const int lchunk = ((lane >> 4) & 1) * 4;
    const int krow   = (lane & 7) + ((lane >> 4) & 1) * 8;
    const int kchunk = ((lane >> 3) & 1) * 4;

    #pragma unroll
    for (int j = 0; j < 8; j++) {
        const int idx = j * 256 + tid;
        const int r = idx >> 5, d0 = (idx & 31) * 4;
        const int srow = qb * 64 + r;
        const float* base = g_q + (size_t)srow * (H_ * D_) + h * D_;
        const float4 x  = *(const float4*)(base + d0);
        const float4 y  = *(const float4*)(base + (d0 ^ 64));
        const float4 c4 = *(const float4*)(cosb + srow * 128 + d0);
        const float4 s4 = *(const float4*)(sinb + srow * 128 + d0);
        const float sg = (d0 < 64) ? -1.f : 1.f;
        const float r0 = x.x * c4.x + sg * y.x * s4.x;
        const float r1 = x.y * c4.y + sg * y.y * s4.y;
        const float r2 = x.z * c4.z + sg * y.z * s4.z;
        const float r3 = x.w * c4.w + sg * y.w * s4.w;
        unsigned l0, l1;
        const unsigned h0 = sp_hi(r0, r1, l0);
        const unsigned h1 = sp_hi(r2, r3, l1);
        Qhi[r * PQ2 + d0 / 2]     = h0;
        Qhi[r * PQ2 + d0 / 2 + 1] = h1;
        Qlo[r * PQ2 + d0 / 2]     = l0;
        Qlo[r * PQ2 + d0 / 2 + 1] = l1;
    }
    if (tid < 64) { Gq[tid] = g_gc[kv * S_ + qb * 64 + tid]; den[tid] = 0.f; }
    __syncthreads();

    const float gq0 = Gq[wm + ly];
    const float gq1 = Gq[wm + ly + 8];
    const float Gq0 = Gq[0];

    float o[8][4];
    #pragma unroll
    for (int ni = 0; ni < 8; ni++)
        #pragma unroll
        for (int r = 0; r < 4; r++) o[ni][r] = 0.f;
    float rs0 = 0.f, rs1 = 0.f;

    for (int kb = qb; kb >= 0; kb--) {
        if (kb < qb && Gq0 - g_gc[kv * S_ + kb * 64 + 63] < DECAY_CUT) break;
        __syncthreads();

        #pragma unroll
        for (int j = 0; j < 8; j++) {
            const int idx = j * 256 + tid;
            const int r = idx >> 5, d0 = (idx & 31) * 4;
            const int srow = kb * 64 + r;
            const float* base = g_k + (size_t)srow * (HKV_ * D_) + kv * D_;
            const float4 x  = *(const float4*)(base + d0);
            const float4 y  = *(const float4*)(base + (d0 ^ 64));
            const float4 c4 = *(const float4*)(cosb + srow * 128 + d0);
            const float4 s4 = *(const float4*)(sinb + srow * 128 + d0);
            const float sg = (d0 < 64) ? -1.f : 1.f;
            const float r0 = x.x * c4.x + sg * y.x * s4.x;
            const float r1 = x.y * c4.y + sg * y.y * s4.y;
            const float r2 = x.z * c4.z + sg * y.z * s4.z;
            const float r3 = x.w * c4.w + sg * y.w * s4.w;
            unsigned l0, l1;
            const unsigned h0 = sp_hi(r0, r1, l0);
            const unsigned h1 = sp_hi(r2, r3, l1);
            Khi[r * PQ2 + d0 / 2]     = h0;
            Khi[r * PQ2 + d0 / 2 + 1] = h1;
            Klo[r * PQ2 + d0 / 2]     = l0;
            Klo[r * PQ2 + d0 / 2 + 1] = l1;
        }
        #pragma unroll
        for (int j = 0; j < 4; j++) {
            const int idx = j * 256 + tid;
            const int kp = idx >> 5, n0 = (idx & 31) * 4;
            const size_t b0 = (size_t)(kb * 64 + 2 * kp) * (HKV_ * D_) + kv * D_ + n0;
            const float4 v0 = *(const float4*)(g_v + b0);
            const float4 v1 = *(const float4*)(g_v + b0 + HKV_ * D_);
            unsigned l0, l1, l2, l3;
            Vhi[kp * PV2 + n0 + 0] = sp_hi(v0.x, v1.x, l0);
            Vhi[kp * PV2 + n0 + 1] = sp_hi(v0.y, v1.y, l1);
            Vhi[kp * PV2 + n0 + 2] = sp_hi(v0.z, v1.z, l2);
            Vhi[kp * PV2 + n0 + 3] = sp_hi(v0.w, v1.w, l3);
            Vlo[kp * PV2 + n0 + 0] = l0;
            Vlo[kp * PV2 + n0 + 1] = l1;
            Vlo[kp * PV2 + n0 + 2] = l2;
            Vlo[kp * PV2 + n0 + 3] = l3;
        }
        if (tid < 64) Gk[tid] = g_gc[kv * S_ + kb * 64 + tid];
        __syncthreads();

        float c[4][4];
        #pragma unroll
        for (int ni = 0; ni < 4; ni++)
            #pragma unroll
            for (int r = 0; r < 4; r++) c[ni][r] = 0.f;
        #pragma unroll
        for (int ks2 = 0; ks2 < 8; ks2++) {
            const int kp0 = ks2 * 8;
            unsigned ah[4], al[4];
            const unsigned qoff = (((wm + lrow) * PQ2 + kp0 + lchunk) << 2);
            ldsm_x4(ah, Qhi_s + qoff);
            ldsm_x4(al, Qlo_s + qoff);
            #pragma unroll
            for (int nb = 0; nb < 2; nb++) {
                const unsigned koff = (((wn + nb * 16 + krow) * PQ2 + kp0 + kchunk) << 2);
                unsigned bh4[4], bl4[4];
                ldsm_x4(bh4, Khi_s + koff);
                ldsm_x4(bl4, Klo_s + koff);
                mma_f16(c[2 * nb],     ah, &bh4[0]);
                mma_f16(c[2 * nb],     al, &bh4[0]);
                mma_f16(c[2 * nb],     ah, &bl4[0]);
                mma_f16(c[2 * nb + 1], ah, &bh4[2]);
                mma_f16(c[2 * nb + 1], al, &bh4[2]);
                mma_f16(c[2 * nb + 1], ah, &bl4[2]);
            }
        }
        float gk0v[4], gk1v[4];
        #pragma unroll
        for (int ni = 0; ni < 4; ni++) {
            const int col = wn + ni * 8 + 2 * lx;
            gk0v[ni] = Gk[col];
            gk1v[ni] = Gk[col + 1];
        }
        __syncthreads();

        const int rg0 = qb * 64 + wm + ly;
        const int rg1 = rg0 + 8;
        #pragma unroll
        for (int ni = 0; ni < 4; ni++) {
            const int col = wn + ni * 8 + 2 * lx;
            const int cg  = kb * 64 + col;
            float t;
            t = c[ni][0] * SCALE_;
            const float v00 = (cg     <= rg0) ? t * t * __expf(gq0 - gk0v[ni]) : 0.f;
            t = c[ni][1] * SCALE_;
            const float v01 = (cg + 1 <= rg0) ? t * t * __expf(gq0 - gk1v[ni]) : 0.f;
            t = c[ni][2] * SCALE_;
            const float v10 = (cg     <= rg1) ? t * t * __expf(gq1 - gk0v[ni]) : 0.f;
            t = c[ni][3] * SCALE_;
            const float v11 = (cg + 1 <= rg1) ? t * t * __expf(gq1 - gk1v[ni]) : 0.f;
            rs0 += v00 + v01;
            rs1 += v10 + v11;
            const int sp = wn / 2 + 4 * ni + lx;
            unsigned l0, l1;
            Shi[(wm + ly) * PS2 + sp]     = sp_hi(v00 * SSCALE, v01 * SSCALE, l0);
            Shi[(wm + ly + 8) * PS2 + sp] = sp_hi(v10 * SSCALE, v11 * SSCALE, l1);
            Slo[(wm + ly) * PS2 + sp]     = l0;
            Slo[(wm + ly + 8) * PS2 + sp] = l1;
        }
        __syncthreads();

        #pragma unroll
        for (int ks2 = 0; ks2 < 4; ks2++) {
            const int jp0 = ks2 * 8;
            unsigned ah[4], al[4];
            const unsigned soff = (((wm + lrow) * PS2 + jp0 + lchunk) << 2);
            ldsm_x4(ah, Shi_s + soff);
            ldsm_x4(al, Slo_s + soff);
            #pragma unroll
            for (int ni = 0; ni < 8; ni++) {
                const int n = wn2 + ni * 8 + ly;
                unsigned bh[2], bl[2];
                bh[0] = Vhi[(jp0 + lx) * PV2 + n];
                bh[1] = Vhi[(jp0 + 4 + lx) * PV2 + n];
                bl[0] = Vlo[(jp0 + lx) * PV2 + n];
                bl[1] = Vlo[(jp0 + 4 + lx) * PV2 + n];
                mma_f16(o[ni], ah, bh);
                mma_f16(o[ni], al, bh);
                mma_f16(o[ni], ah, bl);
            }
        }
    }

    rs0 += __shfl_xor_sync(0xffffffffu, rs0, 1);
    rs0 += __shfl_xor_sync(0xffffffffu, rs0, 2);
    rs1 += __shfl_xor_sync(0xffffffffu, rs1, 1);
    rs1 += __shfl_xor_sync(0xffffffffu, rs1, 2);
    if (lx == 0) {
        atomicAdd(&den[wm + ly], rs0);
        atomicAdd(&den[wm + ly + 8], rs1);
    }
    __syncthreads();

    const float inv0 = INV_SSCALE / fmaxf(den[wm + ly], 1.f);
    const float inv1 = INV_SSCALE / fmaxf(den[wm + ly + 8], 1.f);
    unsigned* ah32 = (unsigned*)g_attnh;
    #pragma unroll
    for (int ni = 0; ni < 8; ni++) {
        const int colg = h * D_ + wn2 + ni * 8 + 2 * lx;
        const size_t i0 = ((size_t)(qb * 64 + wm + ly) * (H_ * D_) + colg) / 2;
        const size_t i1 = ((size_t)(qb * 64 + wm + ly + 8) * (H_ * D_) + colg) / 2;
        ah32[i0] = packh2(o[ni][0] * inv0, o[ni][1] * inv0);
        ah32[i1] = packh2(o[ni][2] * inv1, o[ni][3] * inv1);
    }
}

// ---------------- launch ----------------
extern "C" void kernel_launch(void* const* d_in, const int* in_sizes, int n_in,
                              void* d_out, int out_size) {
    (void)in_sizes; (void)n_in; (void)out_size;
    const float* hs   = (const float*)d_in[0];
    const float* cosb = (const float*)d_in[1];
    const float* sinb = (const float*)d_in[2];
    const float* Wq   = (const float*)d_in[3];
    const float* Wk   = (const float*)d_in[4];
    const float* Wv   = (const float*)d_in[5];
    const float* Wg   = (const float*)d_in[6];
    const float* Wo   = (const float*)d_in[7];
    float* out = (float*)d_out;

    __half *hsh, *attnh;
    unsigned *wqp, *wkp, *wvp, *wop;
    cudaGetSymbolAddress((void**)&hsh,   g_hsh);
    cudaGetSymbolAddress((void**)&attnh, g_attnh);
    cudaGetSymbolAddress((void**)&wqp,   g_wqp);
    cudaGetSymbolAddress((void**)&wkp,   g_wkp);
    cudaGetSymbolAddress((void**)&wvp,   g_wvp);
    cudaGetSymbolAddress((void**)&wop,   g_wop);

    static cudaStream_t s1 = nullptr, s2 = nullptr, s3 = nullptr;
    static cudaEvent_t ev0, ev1, ev2, ev2a, ev3;
    if (!s1) {
        cudaStreamCreateWithFlags(&s1, cudaStreamNonBlocking);
        cudaStreamCreateWithFlags(&s2, cudaStreamNonBlocking);
        cudaStreamCreateWithFlags(&s3, cudaStreamNonBlocking);
        cudaEventCreateWithFlags(&ev0,  cudaEventDisableTiming);
        cudaEventCreateWithFlags(&ev1,  cudaEventDisableTiming);
        cudaEventCreateWithFlags(&ev2,  cudaEventDisableTiming);
        cudaEventCreateWithFlags(&ev2a, cudaEventDisableTiming);
        cudaEventCreateWithFlags(&ev3,  cudaEventDisableTiming);
    }

    cudaFuncSetAttribute(gemm_qkv, cudaFuncAttributeMaxDynamicSharedMemorySize, GEMM_SMEM64);
    cudaFuncSetAttribute(gemm_wo,  cudaFuncAttributeMaxDynamicSharedMemorySize, GEMM_SMEMH);
    cudaFuncSetAttribute(attn_kernel, cudaFuncAttributeMaxDynamicSharedMemorySize, ATTN_SMEM);

    cudaEventRecord(ev0, 0);

    // side stream 2: Wq pair-pack
    cudaStreamWaitEvent(s2, ev0, 0);
    tohalf_pair<<<(HID_/2)*(H_*D_)/4/256, 256, 0, s2>>>(Wq, wqp, H_*D_);
    cudaEventRecord(ev2a, s2);

    // side stream 3: Wk, Wv, then Wo pair-packs
    cudaStreamWaitEvent(s3, ev0, 0);
    tohalf_pair<<<(HID_/2)*(HKV_*D_)/4/256, 256, 0, s3>>>(Wk, wkp, HKV_*D_);
    tohalf_pair<<<(HID_/2)*(HKV_*D_)/4/256, 256, 0, s3>>>(Wv, wvp, HKV_*D_);
    cudaEventRecord(ev3, s3);
    tohalf_pair<<<((H_*D_)/2)*HID_/4/256, 256, 0, s3>>>(Wo, wop, HID_);
    cudaEventRecord(ev2, s3);

    // side stream 1: gate path (exact fp32)
    cudaStreamWaitEvent(s1, ev0, 0);
    gate_proj<<<S_, 128, 0, s1>>>(hs, Wg);
    gcumsum_kernel<<<HKV_, 256, 0, s1>>>();
    cudaEventRecord(ev1, s1);

    // main stream
    tohalf_plain<<<(S_*HID_) / 1024, 256>>>(hs, hsh);
    cudaStreamWaitEvent(0, ev2a, 0);
    cudaStreamWaitEvent(0, ev3, 0);
    gemm_qkv<<<dim3(24, S_ / BM64), 256, GEMM_SMEM64>>>(hsh);

    cudaStreamWaitEvent(0, ev1, 0);
    attn_kernel<<<dim3(S_ / 64, H_), 256, ATTN_SMEM>>>(cosb, sinb);

    cudaStreamWaitEvent(0, ev2, 0);
    gemm_wo<<<dim3(HID_ / BN, S_ / BM), 256, GEMM_SMEMH>>>(attnh, out);
}

// round 17
// speedup vs baseline: 1.1579x; 1.0470x over previous
#include <cuda_runtime.h>
#include <cuda_fp16.h>
#include <math.h>

#define S_     2048
#define HID_   2048
#define H_     16
#define HKV_   4
#define D_     128
#define GROUPS_ 4
#define SCALE_ 0.08838834764831845f   // 128^-0.5
#define DECAY_CUT (-25.0f)
#define SSCALE 512.0f
#define INV_SSCALE (1.0f/512.0f)
#define NTILE 512                      // (S_/64) * H_
#define PGRID 296                      // 2 CTAs/SM * 148 SMs

// ---------------- scratch (no cudaMalloc allowed) ----------------
__device__ float    g_q    [S_*H_*D_];          // unroped; rope applied in attn loader
__device__ float    g_k    [S_*HKV_*D_];
__device__ float    g_v    [S_*HKV_*D_];
__device__ float    g_g    [S_*HKV_];
__device__ float    g_gc   [HKV_*S_];
__device__ __half   g_attnh[S_*H_*D_];
__device__ __half   g_hsh  [S_*HID_];
__device__ unsigned g_wqp  [(HID_/2)*(H_*D_)];
__device__ unsigned g_wkp  [(HID_/2)*(HKV_*D_)];
__device__ unsigned g_wvp  [(HID_/2)*(HKV_*D_)];
__device__ unsigned g_wop  [((H_*D_)/2)*HID_];

// ---------------- helpers ----------------
__device__ __forceinline__ unsigned packh2(float lo, float hi) {
    __half2 h = __floats2half2_rn(lo, hi);
    return *(unsigned*)&h;
}
__device__ __forceinline__ unsigned sp_hi(float a, float b, unsigned& lo) {
    const __half ha = __float2half_rn(a), hb = __float2half_rn(b);
    lo = packh2(a - __half2float(ha), b - __half2float(hb));
    const __half2 hh = __halves2half2(ha, hb);
    return *(unsigned*)&hh;
}
__device__ __forceinline__ void mma_f16(float c[4], const unsigned a[4], const unsigned b[2]) {
    asm volatile("mma.sync.aligned.m16n8k16.row.col.f32.f16.f16.f32 "
        "{%0,%1,%2,%3},{%4,%5,%6,%7},{%8,%9},{%0,%1,%2,%3};"
        : "+f"(c[0]), "+f"(c[1]), "+f"(c[2]), "+f"(c[3])
        : "r"(a[0]), "r"(a[1]), "r"(a[2]), "r"(a[3]), "r"(b[0]), "r"(b[1]));
}
__device__ __forceinline__ void ldsm_x4(unsigned r[4], unsigned saddr) {
    asm volatile("ldmatrix.sync.aligned.m8n8.x4.shared.b16 {%0,%1,%2,%3}, [%4];"
        : "=r"(r[0]), "=r"(r[1]), "=r"(r[2]), "=r"(r[3]) : "r"(saddr));
}
__device__ __forceinline__ void cpa16(void* sp, const void* gp) {
    unsigned s = (unsigned)__cvta_generic_to_shared(sp);
    asm volatile("cp.async.cg.shared.global [%0], [%1], 16;" :: "r"(s), "l"(gp));
}

// ---------------- f32 -> fp16 conversions ----------------
__global__ void tohalf_plain(const float* __restrict__ s, __half* __restrict__ d) {
    const size_t i = ((size_t)blockIdx.x * 256 + threadIdx.x) * 4;
    float4 v = *(const float4*)(s + i);
    uint2 u;
    u.x = packh2(v.x, v.y);
    u.y = packh2(v.z, v.w);
    *(uint2*)((unsigned*)d + i / 2) = u;
}
__global__ void tohalf_pair(const float* __restrict__ W, unsigned* __restrict__ Wp, int N) {
    const int idx = blockIdx.x * 256 + threadIdx.x;
    const int nc4 = N / 4;
    const int kp = idx / nc4, c4 = (idx % nc4) * 4;
    const float4 w0 = *(const float4*)(W + (size_t)(2 * kp) * N + c4);
    const float4 w1 = *(const float4*)(W + (size_t)(2 * kp + 1) * N + c4);
    uint4 u;
    u.x = packh2(w0.x, w1.x);
    u.y = packh2(w0.y, w1.y);
    u.z = packh2(w0.z, w1.z);
    u.w = packh2(w0.w, w1.w);
    *(uint4*)(Wp + (size_t)kp * N + c4) = u;
}

// ---------------- fp16 tensor-core GEMM (R14, proven) ----------------
#define BM 128
#define BN 128
#define NK 64
#define PAH 20
#define PBH 136
#define STG_AH (128*PAH)
#define STG_BH (16*PBH)
#define GEMM_SMEMH (3*(STG_AH+STG_BH)*4)

__device__ __forceinline__ void gemmh_issue(const __half* __restrict__ A,
        const unsigned* __restrict__ Bp, int N, int bm, int bn,
        unsigned* As, unsigned* Bs, int kt,
        int arow, int apair, int brow, int bcol) {
    unsigned* Ad = As + (kt % 3) * STG_AH;
    const unsigned* Ag = (const unsigned*)A + (size_t)(bm + arow) * 1024 + kt * 16 + apair;
    cpa16(Ad + arow * PAH + apair,     Ag);
    cpa16(Ad + arow * PAH + apair + 4, Ag + 4);
    unsigned* Bd = Bs + (kt % 3) * STG_BH;
    const unsigned* Bg = Bp + (size_t)(kt * 16 + brow) * N + bn + bcol;
    cpa16(Bd + brow * PBH + bcol,     Bg);
    cpa16(Bd + brow * PBH + bcol + 4, Bg + 4);
    asm volatile("cp.async.commit_group;");
}

__device__ __forceinline__ void gemmh_core(const __half* __restrict__ A,
        const unsigned* __restrict__ Bp, float* __restrict__ C,
        int N, int bm, int bn, unsigned* As, unsigned* Bs) {
    const int tid  = threadIdx.x;
    const int lane = tid & 31;
    const int warp = tid >> 5;
    const int ly = lane >> 2, lx = lane & 3;
    const int wm = (warp & 3) * 32;
    const int wn = (warp >> 2) * 64;
    const int arow = tid >> 1, apair = (tid & 1) * 8;
    const int brow = tid >> 4, bcol = (tid & 15) * 8;
    const int lrow   = (lane & 7) + ((lane >> 3) & 1) * 8;
    const int lchunk = ((lane >> 4) & 1) * 4;
    const unsigned As_s = (unsigned)__cvta_generic_to_shared(As);

    float acc[2][8][4];
    #pragma unroll
    for (int mi = 0; mi < 2; mi++)
        #pragma unroll
        for (int ni = 0; ni < 8; ni++)
            #pragma unroll
            for (int r = 0; r < 4; r++) acc[mi][ni][r] = 0.f;

    gemmh_issue(A, Bp, N, bm, bn, As, Bs, 0, arow, apair, brow, bcol);
    gemmh_issue(A, Bp, N, bm, bn, As, Bs, 1, arow, apair, brow, bcol);

    for (int kt = 0; kt < NK; kt++) {
        asm volatile("cp.async.wait_group 1;");
        __syncthreads();

        const unsigned AbS = As_s + (((kt % 3) * STG_AH) << 2);
        const unsigned* Bb = Bs + (kt % 3) * STG_BH;
        #pragma unroll
        for (int ks2 = 0; ks2 < 2; ks2++) {
            const int kp0 = ks2 * 8;
            unsigned af[2][4], bf[8][2];
            #pragma unroll
            for (int mi = 0; mi < 2; mi++)
                ldsm_x4(af[mi], AbS + (((wm + mi * 16 + lrow) * PAH + kp0 + lchunk) << 2));
            #pragma unroll
            for (int ni = 0; ni < 8; ni++) {
                const int n = wn + ni * 8 + ly;
                bf[ni][0] = Bb[(kp0 + lx) * PBH + n];
                bf[ni][1] = Bb[(kp0 + 4 + lx) * PBH + n];
            }
            #pragma unroll
            for (int mi = 0; mi < 2; mi++)
                #pragma unroll
                for (int ni = 0; ni < 8; ni++)
                    mma_f16(acc[mi][ni], af[mi], bf[ni]);
        }
        __syncthreads();

        if (kt + 2 < NK)
            gemmh_issue(A, Bp, N, bm, bn, As, Bs, kt + 2, arow, apair, brow, bcol);
        else
            asm volatile("cp.async.commit_group;");
    }

    #pragma unroll
    for (int mi = 0; mi < 2; mi++) {
        const int r0 = bm + wm + mi * 16 + ly;
        #pragma unroll
        for (int ni = 0; ni < 8; ni++) {
            const int c0 = bn + wn + ni * 8 + 2 * lx;
            *(float2*)(C + (size_t)r0 * N + c0)       = make_float2(acc[mi][ni][0], acc[mi][ni][1]);
            *(float2*)(C + (size_t)(r0 + 8) * N + c0) = make_float2(acc[mi][ni][2], acc[mi][ni][3]);
        }
    }
}

__global__ void __launch_bounds__(256, 2) gemm_qkv(const __half* __restrict__ A) {
    extern __shared__ unsigned smu[];
    const int bx = blockIdx.x;
    const unsigned* Bp; float* Cm; int N, bn;
    if (bx < 16)      { Bp = g_wqp; Cm = g_q; N = 2048; bn = bx * 128; }
    else if (bx < 20) { Bp = g_wkp; Cm = g_k; N = 512;  bn = (bx - 16) * 128; }
    else              { Bp = g_wvp; Cm = g_v; N = 512;  bn = (bx - 20) * 128; }
    gemmh_core(A, Bp, Cm, N, blockIdx.y * BM, bn, smu, smu + 3 * STG_AH);
}

__global__ void __launch_bounds__(256, 2) gemm_wo(const __half* __restrict__ A,
        float* __restrict__ C) {
    extern __shared__ unsigned smu[];
    gemmh_core(A, g_wop, C, HID_, blockIdx.y * BM, blockIdx.x * BN, smu, smu + 3 * STG_AH);
}

// ---------------- gate projection (exact fp32) ----------------
__global__ void gate_proj(const float* __restrict__ hs, const float* __restrict__ Wg) {
    const int s = blockIdx.x;
    const int w = threadIdx.x >> 5, l = threadIdx.x & 31;
    const float* row = hs + (size_t)s * HID_;
    float acc = 0.f;
    for (int k = l; k < HID_; k += 32)
        acc = fmaf(row[k], Wg[k * HKV_ + w], acc);
    #pragma unroll
    for (int o = 16; o > 0; o >>= 1)
        acc += __shfl_down_sync(0xffffffffu, acc, o);
    if (l == 0) g_g[s * HKV_ + w] = acc;
}

// ---------------- log-sigmoid + parallel cumsum ----------------
__global__ void gcumsum_kernel() {
    __shared__ float ps[256];
    const int kv = blockIdx.x;
    const int t = threadIdx.x;
    float loc[8]; float s = 0.f;
    #pragma unroll
    for (int i = 0; i < 8; i++) {
        const float x = g_g[(t * 8 + i) * HKV_ + kv];
        const float ls = (x > 0.f) ? -log1pf(__expf(-x)) : x - log1pf(__expf(x));
        loc[i] = ls; s += ls;
    }
    ps[t] = s; __syncthreads();
    for (int o = 1; o < 256; o <<= 1) {
        const float v = (t >= o) ? ps[t - o] : 0.f;
        __syncthreads();
        ps[t] += v;
        __syncthreads();
    }
    float run = (t > 0) ? ps[t - 1] : 0.f;
    #pragma unroll
    for (int i = 0; i < 8; i++) {
        run += loc[i];
        g_gc[kv * S_ + t * 8 + i] = run;
    }
}

// ---------------- fp16-split tensor-core power attention (persistent) -----
#define PQ2 68
#define PS2 36
#define PV2 136
#define ATTN_SMEM ((4*64*PQ2 + 2*32*PV2 + 192) * 4)   // 105216 B

__global__ void __launch_bounds__(256, 2) attn_kernel(
        const float* __restrict__ cosb, const float* __restrict__ sinb) {
    extern __shared__ unsigned smu[];
    unsigned* Qhi = smu;
    unsigned* Qlo = Qhi + 64 * PQ2;
    unsigned* Khi = Qlo + 64 * PQ2;
    unsigned* Klo = Khi + 64 * PQ2;
    unsigned* Vhi = Klo + 64 * PQ2;
    unsigned* Vlo = Vhi + 32 * PV2;
    float* Gq  = (float*)(Vlo + 32 * PV2);
    float* Gk  = Gq + 64;
    float* den = Gk + 64;
    unsigned* Shi = Khi;
    unsigned* Slo = Klo;

    const unsigned Qhi_s = (unsigned)__cvta_generic_to_shared(Qhi);
    const unsigned Qlo_s = Qhi_s + 64 * PQ2 * 4;
    const unsigned Khi_s = Qlo_s + 64 * PQ2 * 4;
    const unsigned Klo_s = Khi_s + 64 * PQ2 * 4;
    const unsigned Shi_s = Khi_s;
    const unsigned Slo_s = Klo_s;

    const int tid  = threadIdx.x;
    const int lane = tid & 31, warp = tid >> 5;
    const int ly = lane >> 2, lx = lane & 3;
    const int wm  = (warp & 3) * 16;
    const int wn  = (warp >> 2) * 32;
    const int wn2 = (warp >> 2) * 64;
    const int lrow   = (lane & 7) + ((lane >> 3) & 1) * 8;
    const int lchunk = ((lane >> 4) & 1) * 4;
    const int krow   = (lane & 7) + ((lane >> 4) & 1) * 8;
    const int kchunk = ((lane >> 3) & 1) * 4;

    // persistent loop over (qb, h) tiles, big-qb first
    for (int t = blockIdx.x; t < NTILE; t += PGRID) {
        const int qb = (S_ / 64) - 1 - (t >> 4);
        const int h  = t & 15;
        const int kv = h / GROUPS_;

        __syncthreads();   // previous tile fully done with smem
        #pragma unroll
        for (int j = 0; j < 8; j++) {
            const int idx = j * 256 + tid;
            const int r = idx >> 5, d0 = (idx & 31) * 4;
            const int srow = qb * 64 + r;
            const float* base = g_q + (size_t)srow * (H_ * D_) + h * D_;
            const float4 x  = *(const float4*)(base + d0);
            const float4 y  = *(const float4*)(base + (d0 ^ 64));
            const float4 c4 = *(const float4*)(cosb + srow * 128 + d0);
            const float4 s4 = *(const float4*)(sinb + srow * 128 + d0);
            const float sg = (d0 < 64) ? -1.f : 1.f;
            const float r0 = x.x * c4.x + sg * y.x * s4.x;
            const float r1 = x.y * c4.y + sg * y.y * s4.y;
            const float r2 = x.z * c4.z + sg * y.z * s4.z;
            const float r3 = x.w * c4.w + sg * y.w * s4.w;
            unsigned l0, l1;
            const unsigned h0 = sp_hi(r0, r1, l0);
            const unsigned h1 = sp_hi(r2, r3, l1);
            Qhi[r * PQ2 + d0 / 2]     = h0;
            Qhi[r * PQ2 + d0 / 2 + 1] = h1;
            Qlo[r * PQ2 + d0 / 2]     = l0;
            Qlo[r * PQ2 + d0 / 2 + 1] = l1;
        }
        if (tid < 64) { Gq[tid] = g_gc[kv * S_ + qb * 64 + tid]; den[tid] = 0.f; }
        __syncthreads();

        const float gq0 = Gq[wm + ly];
        const float gq1 = Gq[wm + ly + 8];
        const float Gq0 = Gq[0];

        float o[8][4];
        #pragma unroll
        for (int ni = 0; ni < 8; ni++)
            #pragma unroll
            for (int r = 0; r < 4; r++) o[ni][r] = 0.f;
        float rs0 = 0.f, rs1 = 0.f;

        for (int kb = qb; kb >= 0; kb--) {
            if (kb < qb && Gq0 - g_gc[kv * S_ + kb * 64 + 63] < DECAY_CUT) break;
            __syncthreads();

            #pragma unroll
            for (int j = 0; j < 8; j++) {
                const int idx = j * 256 + tid;
                const int r = idx >> 5, d0 = (idx & 31) * 4;
                const int srow = kb * 64 + r;
                const float* base = g_k + (size_t)srow * (HKV_ * D_) + kv * D_;
                const float4 x  = *(const float4*)(base + d0);
                const float4 y  = *(const float4*)(base + (d0 ^ 64));
                const float4 c4 = *(const float4*)(cosb + srow * 128 + d0);
                const float4 s4 = *(const float4*)(sinb + srow * 128 + d0);
                const float sg = (d0 < 64) ? -1.f : 1.f;
                const float r0 = x.x * c4.x + sg * y.x * s4.x;
                const float r1 = x.y * c4.y + sg * y.y * s4.y;
                const float r2 = x.z * c4.z + sg * y.z * s4.z;
                const float r3 = x.w * c4.w + sg * y.w * s4.w;
                unsigned l0, l1;
                const unsigned h0 = sp_hi(r0, r1, l0);
                const unsigned h1 = sp_hi(r2, r3, l1);
                Khi[r * PQ2 + d0 / 2]     = h0;
                Khi[r * PQ2 + d0 / 2 + 1] = h1;
                Klo[r * PQ2 + d0 / 2]     = l0;
                Klo[r * PQ2 + d0 / 2 + 1] = l1;
            }
            #pragma unroll
            for (int j = 0; j < 4; j++) {
                const int idx = j * 256 + tid;
                const int kp = idx >> 5, n0 = (idx & 31) * 4;
                const size_t b0 = (size_t)(kb * 64 + 2 * kp) * (HKV_ * D_) + kv * D_ + n0;
                const float4 v0 = *(const float4*)(g_v + b0);
                const float4 v1 = *(const float4*)(g_v + b0 + HKV_ * D_);
                unsigned l0, l1, l2, l3;
                Vhi[kp * PV2 + n0 + 0] = sp_hi(v0.x, v1.x, l0);
                Vhi[kp * PV2 + n0 + 1] = sp_hi(v0.y, v1.y, l1);
                Vhi[kp * PV2 + n0 + 2] = sp_hi(v0.z, v1.z, l2);
                Vhi[kp * PV2 + n0 + 3] = sp_hi(v0.w, v1.w, l3);
                Vlo[kp * PV2 + n0 + 0] = l0;
                Vlo[kp * PV2 + n0 + 1] = l1;
                Vlo[kp * PV2 + n0 + 2] = l2;
                Vlo[kp * PV2 + n0 + 3] = l3;
            }
            if (tid < 64) Gk[tid] = g_gc[kv * S_ + kb * 64 + tid];
            __syncthreads();

            float c[4][4];
            #pragma unroll
            for (int ni = 0; ni < 4; ni++)
                #pragma unroll
                for (int r = 0; r < 4; r++) c[ni][r] = 0.f;
            #pragma unroll
            for (int ks2 = 0; ks2 < 8; ks2++) {
                const int kp0 = ks2 * 8;
                unsigned ah[4], al[4];
                const unsigned qoff = (((wm + lrow) * PQ2 + kp0 + lchunk) << 2);
                ldsm_x4(ah, Qhi_s + qoff);
                ldsm_x4(al, Qlo_s + qoff);
                #pragma unroll
                for (int nb = 0; nb < 2; nb++) {
                    const unsigned koff = (((wn + nb * 16 + krow) * PQ2 + kp0 + kchunk) << 2);
                    unsigned bh4[4], bl4[4];
                    ldsm_x4(bh4, Khi_s + koff);
                    ldsm_x4(bl4, Klo_s + koff);
                    mma_f16(c[2 * nb],     ah, &bh4[0]);
                    mma_f16(c[2 * nb],     al, &bh4[0]);
                    mma_f16(c[2 * nb],     ah, &bl4[0]);
                    mma_f16(c[2 * nb + 1], ah, &bh4[2]);
                    mma_f16(c[2 * nb + 1], al, &bh4[2]);
                    mma_f16(c[2 * nb + 1], ah, &bl4[2]);
                }
            }
            float gk0v[4], gk1v[4];
            #pragma unroll
            for (int ni = 0; ni < 4; ni++) {
                const int col = wn + ni * 8 + 2 * lx;
                gk0v[ni] = Gk[col];
                gk1v[ni] = Gk[col + 1];
            }
            __syncthreads();

            const int rg0 = qb * 64 + wm + ly;
            const int rg1 = rg0 + 8;
            #pragma unroll
            for (int ni = 0; ni < 4; ni++) {
                const int col = wn + ni * 8 + 2 * lx;
                const int cg  = kb * 64 + col;
                float tt;
                tt = c[ni][0] * SCALE_;
                const float v00 = (cg     <= rg0) ? tt * tt * __expf(gq0 - gk0v[ni]) : 0.f;
                tt = c[ni][1] * SCALE_;
                const float v01 = (cg + 1 <= rg0) ? tt * tt * __expf(gq0 - gk1v[ni]) : 0.f;
                tt = c[ni][2] * SCALE_;
                const float v10 = (cg     <= rg1) ? tt * tt * __expf(gq1 - gk0v[ni]) : 0.f;
                tt = c[ni][3] * SCALE_;
                const float v11 = (cg + 1 <= rg1) ? tt * tt * __expf(gq1 - gk1v[ni]) : 0.f;
                rs0 += v00 + v01;
                rs1 += v10 + v11;
                const int sp = wn / 2 + 4 * ni + lx;
                unsigned l0, l1;
                Shi[(wm + ly) * PS2 + sp]     = sp_hi(v00 * SSCALE, v01 * SSCALE, l0);
                Shi[(wm + ly + 8) * PS2 + sp] = sp_hi(v10 * SSCALE, v11 * SSCALE, l1);
                Slo[(wm + ly) * PS2 + sp]     = l0;
                Slo[(wm + ly + 8) * PS2 + sp] = l1;
            }
            __syncthreads();

            #pragma unroll
            for (int ks2 = 0; ks2 < 4; ks2++) {
                const int jp0 = ks2 * 8;
                unsigned ah[4], al[4];
                const unsigned soff = (((wm + lrow) * PS2 + jp0 + lchunk) << 2);
                ldsm_x4(ah, Shi_s + soff);
                ldsm_x4(al, Slo_s + soff);
                #pragma unroll
                for (int ni = 0; ni < 8; ni++) {
                    const int n = wn2 + ni * 8 + ly;
                    unsigned bh[2], bl[2];
                    bh[0] = Vhi[(jp0 + lx) * PV2 + n];
                    bh[1] = Vhi[(jp0 + 4 + lx) * PV2 + n];
                    bl[0] = Vlo[(jp0 + lx) * PV2 + n];
                    bl[1] = Vlo[(jp0 + 4 + lx) * PV2 + n];
                    mma_f16(o[ni], ah, bh);
                    mma_f16(o[ni], al, bh);
                    mma_f16(o[ni], ah, bl);
                }
            }
        }

        float r0s = rs0, r1s = rs1;
        r0s += __shfl_xor_sync(0xffffffffu, r0s, 1);
        r0s += __shfl_xor_sync(0xffffffffu, r0s, 2);
        r1s += __shfl_xor_sync(0xffffffffu, r1s, 1);
        r1s += __shfl_xor_sync(0xffffffffu, r1s, 2);
        if (lx == 0) {
            atomicAdd(&den[wm + ly], r0s);
            atomicAdd(&den[wm + ly + 8], r1s);
        }
        __syncthreads();

        const float inv0 = INV_SSCALE / fmaxf(den[wm + ly], 1.f);
        const float inv1 = INV_SSCALE / fmaxf(den[wm + ly + 8], 1.f);
        unsigned* ah32 = (unsigned*)g_attnh;
        #pragma unroll
        for (int ni = 0; ni < 8; ni++) {
            const int colg = h * D_ + wn2 + ni * 8 + 2 * lx;
            const size_t i0 = ((size_t)(qb * 64 + wm + ly) * (H_ * D_) + colg) / 2;
            const size_t i1 = ((size_t)(qb * 64 + wm + ly + 8) * (H_ * D_) + colg) / 2;
            ah32[i0] = packh2(o[ni][0] * inv0, o[ni][1] * inv0);
            ah32[i1] = packh2(o[ni][2] * inv1, o[ni][3] * inv1);
        }
    }
}

// ---------------- launch ----------------
extern "C" void kernel_launch(void* const* d_in, const int* in_sizes, int n_in,
                              void* d_out, int out_size) {
    (void)in_sizes; (void)n_in; (void)out_size;
    const float* hs   = (const float*)d_in[0];
    const float* cosb = (const float*)d_in[1];
    const float* sinb = (const float*)d_in[2];
    const float* Wq   = (const float*)d_in[3];
    const float* Wk   = (const float*)d_in[4];
    const float* Wv   = (const float*)d_in[5];
    const float* Wg   = (const float*)d_in[6];
    const float* Wo   = (const float*)d_in[7];
    float* out = (float*)d_out;

    __half *hsh, *attnh;
    unsigned *wqp, *wkp, *wvp, *wop;
    cudaGetSymbolAddress((void**)&hsh,   g_hsh);
    cudaGetSymbolAddress((void**)&attnh, g_attnh);
    cudaGetSymbolAddress((void**)&wqp,   g_wqp);
    cudaGetSymbolAddress((void**)&wkp,   g_wkp);
    cudaGetSymbolAddress((void**)&wvp,   g_wvp);
    cudaGetSymbolAddress((void**)&wop,   g_wop);

    static cudaStream_t s1 = nullptr, s2 = nullptr, s3 = nullptr;
    static cudaEvent_t ev0, ev1, ev2, ev2a, ev3;
    if (!s1) {
        cudaStreamCreateWithFlags(&s1, cudaStreamNonBlocking);
        cudaStreamCreateWithFlags(&s2, cudaStreamNonBlocking);
        cudaStreamCreateWithFlags(&s3, cudaStreamNonBlocking);
        cudaEventCreateWithFlags(&ev0,  cudaEventDisableTiming);
        cudaEventCreateWithFlags(&ev1,  cudaEventDisableTiming);
        cudaEventCreateWithFlags(&ev2,  cudaEventDisableTiming);
        cudaEventCreateWithFlags(&ev2a, cudaEventDisableTiming);
        cudaEventCreateWithFlags(&ev3,  cudaEventDisableTiming);
    }

    cudaFuncSetAttribute(gemm_qkv, cudaFuncAttributeMaxDynamicSharedMemorySize, GEMM_SMEMH);
    cudaFuncSetAttribute(gemm_wo,  cudaFuncAttributeMaxDynamicSharedMemorySize, GEMM_SMEMH);
    cudaFuncSetAttribute(attn_kernel, cudaFuncAttributeMaxDynamicSharedMemorySize, ATTN_SMEM);

    cudaEventRecord(ev0, 0);

    // side stream 2: Wq pair-pack
    cudaStreamWaitEvent(s2, ev0, 0);
    tohalf_pair<<<(HID_/2)*(H_*D_)/4/256, 256, 0, s2>>>(Wq, wqp, H_*D_);
    cudaEventRecord(ev2a, s2);

    // side stream 3: Wk, Wv, then Wo pair-packs
    cudaStreamWaitEvent(s3, ev0, 0);
    tohalf_pair<<<(HID_/2)*(HKV_*D_)/4/256, 256, 0, s3>>>(Wk, wkp, HKV_*D_);
    tohalf_pair<<<(HID_/2)*(HKV_*D_)/4/256, 256, 0, s3>>>(Wv, wvp, HKV_*D_);
    cudaEventRecord(ev3, s3);
    tohalf_pair<<<((H_*D_)/2)*HID_/4/256, 256, 0, s3>>>(Wo, wop, HID_);
    cudaEventRecord(ev2, s3);

    // side stream 1: gate path (exact fp32)
    cudaStreamWaitEvent(s1, ev0, 0);
    gate_proj<<<S_, 128, 0, s1>>>(hs, Wg);
    gcumsum_kernel<<<HKV_, 256, 0, s1>>>();
    cudaEventRecord(ev1, s1);

    // main stream
    tohalf_plain<<<(S_*HID_) / 1024, 256>>>(hs, hsh);
    cudaStreamWaitEvent(0, ev2a, 0);
    cudaStreamWaitEvent(0, ev3, 0);
    gemm_qkv<<<dim3(24, S_ / BM), 256, GEMM_SMEMH>>>(hsh);

    cudaStreamWaitEvent(0, ev1, 0);
    attn_kernel<<<PGRID, 256, ATTN_SMEM>>>(cosb, sinb);

    cudaStreamWaitEvent(0, ev2, 0);
    gemm_wo<<<dim3(HID_ / BN, S_ / BM), 256, GEMM_SMEMH>>>(attnh, out);
}